// round 1
// baseline (speedup 1.0000x reference)
#include <cuda_runtime.h>
#include <cstdint>
#include <math.h>

#define BDIM 128
#define RDIM 36
#define WDIM 64
#define DDIM 1024
#define KC 32
#define NCHUNK (DDIM / KC)
#define CAP_STRIDE (KC + 2)              // 34 floats: 2-way-conflict floor for LDS.64
#define IM_FLOATS (RDIM * KC)            // 1152
#define CAP_FLOATS (WDIM * CAP_STRIDE)   // 2176

typedef unsigned long long ull;

// -------- scratch (module globals: allowed; no cudaMalloc anywhere) --------
__device__ float g_A0[(size_t)BDIM * BDIM * RDIM * WDIM];  // raw im·cap dots, tile-contiguous (151MB)
__device__ float g_gram[BDIM * RDIM * RDIM];
__device__ float g_ncap[BDIM * WDIM];
__device__ float g_scores[BDIM * BDIM];

// -------- PTX helpers --------
__device__ __forceinline__ ull fma2(ull a, ull b, ull c) {
    ull d;
    asm("fma.rn.f32x2 %0, %1, %2, %3;" : "=l"(d) : "l"(a), "l"(b), "l"(c));
    return d;
}
__device__ __forceinline__ unsigned su32(const void* p) {
    unsigned a;
    asm("{ .reg .u64 t; cvta.to.shared.u64 t, %1; cvt.u32.u64 %0, t; }" : "=r"(a) : "l"(p));
    return a;
}
__device__ __forceinline__ void cpa16(void* dst, const void* src) {
    asm volatile("cp.async.cg.shared.global [%0], [%1], 16;" :: "r"(su32(dst)), "l"(src));
}
__device__ __forceinline__ void cpa8(void* dst, const void* src) {
    asm volatile("cp.async.ca.shared.global [%0], [%1], 8;" :: "r"(su32(dst)), "l"(src));
}
__device__ __forceinline__ void cp_commit() { asm volatile("cp.async.commit_group;"); }
__device__ __forceinline__ void cp_wait1()  { asm volatile("cp.async.wait_group 1;"); }

// ============================================================================
// Kernel 1: per-image Gram matrices G[i][r1][r2] = im_i[r1] . im_i[r2]
// ============================================================================
__global__ void __launch_bounds__(256) gram_kernel(const float* __restrict__ im) {
    const int i = blockIdx.x;
    const int warp = threadIdx.x >> 5, lane = threadIdx.x & 31;
    const float4* base = (const float4*)(im + (size_t)i * RDIM * DDIM);
    for (int p = warp; p < RDIM * RDIM; p += 8) {
        const int r1 = p / RDIM, r2 = p - r1 * RDIM;
        const float4* A = base + r1 * (DDIM / 4);
        const float4* B = base + r2 * (DDIM / 4);
        float sum = 0.f;
        for (int q = lane; q < DDIM / 4; q += 32) {
            float4 a = A[q], b = B[q];
            sum += a.x * b.x + a.y * b.y + a.z * b.z + a.w * b.w;
        }
        #pragma unroll
        for (int o = 16; o; o >>= 1) sum += __shfl_down_sync(0xffffffffu, sum, o);
        if (lane == 0) g_gram[i * (RDIM * RDIM) + p] = sum;
    }
}

// ============================================================================
// Kernel 2: caption word norms ncap[j][w] = ||s[j][w][:]||
// ============================================================================
__global__ void __launch_bounds__(256) ncap_kernel(const float* __restrict__ s) {
    const int gw = blockIdx.x * 8 + (threadIdx.x >> 5);  // 0..8191
    const int lane = threadIdx.x & 31;
    const float4* row = (const float4*)(s + (size_t)gw * DDIM);
    float sum = 0.f;
    for (int q = lane; q < DDIM / 4; q += 32) {
        float4 a = row[q];
        sum += a.x * a.x + a.y * a.y + a.z * a.z + a.w * a.w;
    }
    #pragma unroll
    for (int o = 16; o; o >>= 1) sum += __shfl_down_sync(0xffffffffu, sum, o);
    if (lane == 0) g_ncap[gw] = sqrtf(sum);
}

// ============================================================================
// Kernel 3: big GEMM  A0[i,j,r,w] = sum_d im[i,r,d] * s[j,w,d]
// One CTA per (i,j) pair, 36x64 tile. Packed f32x2 FMA with even/odd-k split.
// ============================================================================
__global__ void __launch_bounds__(192) gemm_kernel(const float* __restrict__ im,
                                                   const float* __restrict__ s) {
    __shared__ float imc[2 * IM_FLOATS];    // [buf][r][k], broadcast reads
    __shared__ float capc[2 * CAP_FLOATS];  // [buf][w][k] stride 34

    const int tid = threadIdx.x;
    const int j = blockIdx.x, i = blockIdx.y;
    const int w = tid & 63;
    const int r0 = (tid >> 6) * 12;
    const float* imG = im + (size_t)i * (RDIM * DDIM);
    const float* sG  = s  + (size_t)j * (WDIM * DDIM);

    ull acc[12];
    #pragma unroll
    for (int rr = 0; rr < 12; ++rr) acc[rr] = 0ULL;

    // preload chunk 0 into buf 0
    for (int idx = tid; idx < IM_FLOATS / 4; idx += 192) {       // 288 float4
        int r = idx >> 3, q = idx & 7;                            // 8 float4 per row
        cpa16(imc + r * KC + q * 4, imG + r * DDIM + q * 4);
    }
    for (int idx = tid; idx < WDIM * KC / 2; idx += 192) {       // 1024 x 8B
        int ww = idx >> 4, h = idx & 15;
        cpa8(capc + ww * CAP_STRIDE + h * 2, sG + ww * DDIM + h * 2);
    }
    cp_commit();

    for (int c = 0; c < NCHUNK; ++c) {
        const int nb = (c + 1) & 1;
        if (c + 1 < NCHUNK) {
            const int koff = (c + 1) * KC;
            for (int idx = tid; idx < IM_FLOATS / 4; idx += 192) {
                int r = idx >> 3, q = idx & 7;
                cpa16(imc + nb * IM_FLOATS + r * KC + q * 4, imG + r * DDIM + koff + q * 4);
            }
            for (int idx = tid; idx < WDIM * KC / 2; idx += 192) {
                int ww = idx >> 4, h = idx & 15;
                cpa8(capc + nb * CAP_FLOATS + ww * CAP_STRIDE + h * 2,
                     sG + ww * DDIM + koff + h * 2);
            }
        }
        cp_commit();
        cp_wait1();
        __syncthreads();

        const int b = c & 1;
        const float* imb  = imc  + b * IM_FLOATS  + r0 * KC;
        const float* capb = capc + b * CAP_FLOATS + w * CAP_STRIDE;
        #pragma unroll
        for (int k = 0; k < KC; k += 4) {
            ull b01 = *(const ull*)(capb + k);      // (cap[k], cap[k+1])
            ull b23 = *(const ull*)(capb + k + 2);
            #pragma unroll
            for (int rr = 0; rr < 12; ++rr) {
                ulonglong2 a = *(const ulonglong2*)(imb + rr * KC + k);  // broadcast LDS.128
                acc[rr] = fma2(a.x, b01, acc[rr]);  // even-k half
                acc[rr] = fma2(a.y, b23, acc[rr]);  // odd-k half
            }
        }
        __syncthreads();
    }

    float* outp = g_A0 + ((size_t)(i * BDIM + j) * RDIM + r0) * WDIM + w;
    #pragma unroll
    for (int rr = 0; rr < 12; ++rr) {
        float lo, hi;
        asm("mov.b64 {%0,%1}, %2;" : "=f"(lo), "=f"(hi) : "l"(acc[rr]));
        outp[rr * WDIM] = lo + hi;
    }
}

// ============================================================================
// Kernel 4: per-pair epilogue -> scores[i][j]
// leaky+mask+l2norm+softmax, num = sum_r a*A0, ||wei||^2 = a^T G a, cosine, LSE
// ============================================================================
__global__ void __launch_bounds__(64) scores_kernel(const int* __restrict__ s_l) {
    __shared__ float A0s[RDIM * 65];
    __shared__ float es [RDIM * 65];
    __shared__ float Gs [RDIM * RDIM];
    __shared__ float rn [RDIM];
    __shared__ float part[2];

    const int j = blockIdx.x, i = blockIdx.y;
    const int tid = threadIdx.x;
    const int L = s_l[j];

    const float* pa = g_A0 + (size_t)(i * BDIM + j) * (RDIM * WDIM);
    for (int idx = tid; idx < RDIM * WDIM; idx += 64) {
        int r = idx >> 6, w = idx & 63;
        A0s[r * 65 + w] = pa[idx];
    }
    const float* pg = g_gram + i * (RDIM * RDIM);
    for (int idx = tid; idx < RDIM * RDIM; idx += 64) Gs[idx] = pg[idx];
    __syncthreads();

    // row l2-norms over valid words; fold the 9x softmax scale in
    if (tid < RDIM) {
        float sum = 0.f;
        for (int w2 = 0; w2 < L; ++w2) {
            float x = A0s[tid * 65 + w2];
            x = (x > 0.f) ? x : 0.1f * x;
            sum += x * x;
        }
        rn[tid] = 9.0f / (sqrtf(sum) + 1e-8f);
    }
    __syncthreads();

    float t = 0.f;
    if (tid < L) {
        const int w = tid;
        // logits + max
        float m = -1e30f;
        for (int r = 0; r < RDIM; ++r) {
            float x = A0s[r * 65 + w];
            x = (x > 0.f) ? x : 0.1f * x;
            x *= rn[r];
            es[r * 65 + w] = x;
            m = fmaxf(m, x);
        }
        // exp + sum (unnormalized softmax weights e)
        float se = 0.f;
        for (int r = 0; r < RDIM; ++r) {
            float e = __expf(es[r * 65 + w] - m);
            es[r * 65 + w] = e;
            se += e;
        }
        // num = sum_r e_r * A0[r][w]
        float num = 0.f;
        for (int r = 0; r < RDIM; ++r) num += es[r * 65 + w] * A0s[r * 65 + w];
        // quad = e^T G e
        float quad = 0.f;
        for (int r = 0; r < RDIM; ++r) {
            float v = 0.f;
            const float* gr = Gs + r * RDIM;
            #pragma unroll 4
            for (int r2 = 0; r2 < RDIM; ++r2) v += gr[r2] * es[r2 * 65 + w];
            quad += v * es[r * 65 + w];
        }
        quad = fmaxf(quad, 0.f);
        float nwei  = sqrtf(quad) / se;   // ||wei_w||
        float numn  = num / se;
        float ncv   = g_ncap[j * WDIM + w];
        float denom = fmaxf(ncv * nwei, 1e-8f);
        float rowv  = numn / denom;
        t = __expf(6.0f * rowv);
    }
    #pragma unroll
    for (int o = 16; o; o >>= 1) t += __shfl_down_sync(0xffffffffu, t, o);
    if ((tid & 31) == 0) part[tid >> 5] = t;
    __syncthreads();
    if (tid == 0) g_scores[i * BDIM + j] = logf(part[0] + part[1]) / 6.0f;
}

// ============================================================================
// Kernel 5: hardest-negative hinge loss over scores [128,128]
// ============================================================================
__global__ void __launch_bounds__(128) loss_kernel(float* __restrict__ out) {
    __shared__ float red[128];
    const int t = threadIdx.x;
    const float di = g_scores[t * BDIM + t];
    float ms = 0.f, mi = 0.f;
    for (int k = 0; k < BDIM; ++k) {
        if (k == t) continue;
        ms = fmaxf(ms, fmaxf(0.f, 0.2f + g_scores[t * BDIM + k] - di));  // cost_s row t
        mi = fmaxf(mi, fmaxf(0.f, 0.2f + g_scores[k * BDIM + t] - di));  // cost_im col t
    }
    red[t] = ms + mi;
    __syncthreads();
    for (int st = 64; st > 0; st >>= 1) {
        if (t < st) red[t] += red[t + st];
        __syncthreads();
    }
    if (t == 0) out[0] = red[0];
}

// ============================================================================
extern "C" void kernel_launch(void* const* d_in, const int* in_sizes, int n_in,
                              void* d_out, int out_size) {
    const float* im = (const float*)d_in[0];
    const float* s  = (const float*)d_in[1];
    const int*   sl = (const int*)d_in[2];
    float* out = (float*)d_out;

    gram_kernel<<<BDIM, 256>>>(im);
    ncap_kernel<<<(BDIM * WDIM) / 8, 256>>>(s);
    gemm_kernel<<<dim3(BDIM, BDIM), 192>>>(im, s);
    scores_kernel<<<dim3(BDIM, BDIM), 64>>>(sl);
    loss_kernel<<<1, 128>>>(out);
}

// round 5
// speedup vs baseline: 2.9924x; 2.9924x over previous
#include <cuda_runtime.h>
#include <cuda_bf16.h>
#include <cstdint>
#include <math.h>

#define BDIM 128
#define RDIM 36
#define WDIM 64
#define DDIM 1024

// ---------------- device globals (no runtime allocation) ----------------
__device__ __align__(128) float g_C[(size_t)BDIM * RDIM * BDIM * WDIM];   // [4608][8192]
__device__ __align__(128) __nv_bfloat16 g_Ah[(size_t)BDIM * RDIM * DDIM];
__device__ __align__(128) __nv_bfloat16 g_Al[(size_t)BDIM * RDIM * DDIM];
__device__ __align__(128) __nv_bfloat16 g_Bh[(size_t)BDIM * WDIM * DDIM];
__device__ __align__(128) __nv_bfloat16 g_Bl[(size_t)BDIM * WDIM * DDIM];
__device__ float g_gram[BDIM * RDIM * RDIM];
__device__ float g_ncap[BDIM * WDIM];
__device__ float g_scores[BDIM * BDIM];

// ---------------- PTX helpers (baseline compute_103-safe only) ----------------
__device__ __forceinline__ unsigned su32(const void* p) {
    unsigned a;
    asm("{ .reg .u64 t; cvta.to.shared.u64 t, %1; cvt.u32.u64 %0, t; }" : "=r"(a) : "l"(p));
    return a;
}
__device__ __forceinline__ void cpa16_s(unsigned dst, const void* src) {
    asm volatile("cp.async.cg.shared.global [%0], [%1], 16;" :: "r"(dst), "l"(src));
}
__device__ __forceinline__ void cp_commit() { asm volatile("cp.async.commit_group;"); }
__device__ __forceinline__ unsigned lds32(unsigned addr) {
    unsigned v;
    asm volatile("ld.shared.b32 %0, [%1];" : "=r"(v) : "r"(addr));
    return v;
}

#define MMA16816(d, a, b0v, b1v) \
    asm volatile("mma.sync.aligned.m16n8k16.row.col.f32.bf16.bf16.f32 " \
                 "{%0,%1,%2,%3}, {%4,%5,%6,%7}, {%8,%9}, {%0,%1,%2,%3};" \
                 : "+f"((d)[0]), "+f"((d)[1]), "+f"((d)[2]), "+f"((d)[3]) \
                 : "r"((a)[0]), "r"((a)[1]), "r"((a)[2]), "r"((a)[3]), "r"(b0v), "r"(b1v))

// ============================================================================
// Convert fp32 -> (hi, lo) bf16 split.
// IMPORTANT: device globals referenced DIRECTLY in device code (host-side
// symbol decay gives the host shadow address, which GB300's ATS silently
// accepts — that was the R3/R4 correctness bug).
// ============================================================================
__device__ __forceinline__ void split_write(const float* __restrict__ src,
                                            __nv_bfloat16* __restrict__ hi,
                                            __nv_bfloat16* __restrict__ lo,
                                            int i) {
    float4 x = ((const float4*)src)[i];
    __nv_bfloat16 h0 = __float2bfloat16(x.x);
    __nv_bfloat16 h1 = __float2bfloat16(x.y);
    __nv_bfloat16 h2 = __float2bfloat16(x.z);
    __nv_bfloat16 h3 = __float2bfloat16(x.w);
    __nv_bfloat16 l0 = __float2bfloat16(x.x - __bfloat162float(h0));
    __nv_bfloat16 l1 = __float2bfloat16(x.y - __bfloat162float(h1));
    __nv_bfloat16 l2 = __float2bfloat16(x.z - __bfloat162float(h2));
    __nv_bfloat16 l3 = __float2bfloat16(x.w - __bfloat162float(h3));
    __nv_bfloat162* hp = (__nv_bfloat162*)hi;
    __nv_bfloat162* lp = (__nv_bfloat162*)lo;
    hp[2 * i]     = __nv_bfloat162(h0, h1);
    hp[2 * i + 1] = __nv_bfloat162(h2, h3);
    lp[2 * i]     = __nv_bfloat162(l0, l1);
    lp[2 * i + 1] = __nv_bfloat162(l2, l3);
}

__global__ void __launch_bounds__(256) convert_im_kernel(const float* __restrict__ im) {
    int i = blockIdx.x * 256 + threadIdx.x;                 // over float4s
    if (i >= BDIM * RDIM * DDIM / 4) return;
    split_write(im, g_Ah, g_Al, i);
}

__global__ void __launch_bounds__(256) convert_s_kernel(const float* __restrict__ s) {
    int i = blockIdx.x * 256 + threadIdx.x;
    if (i >= BDIM * WDIM * DDIM / 4) return;
    split_write(s, g_Bh, g_Bl, i);
}

// ============================================================================
// Gram matrices (symmetric)
// ============================================================================
__global__ void __launch_bounds__(256) gram_kernel(const float* __restrict__ im) {
    const int i = blockIdx.x;
    const int warp = threadIdx.x >> 5, lane = threadIdx.x & 31;
    const float4* base = (const float4*)(im + (size_t)i * RDIM * DDIM);
    for (int p = warp; p < RDIM * RDIM; p += 8) {
        const int r1 = p / RDIM, r2 = p - r1 * RDIM;
        if (r1 > r2) continue;
        const float4* A = base + r1 * (DDIM / 4);
        const float4* B = base + r2 * (DDIM / 4);
        float sum = 0.f;
        for (int q = lane; q < DDIM / 4; q += 32) {
            float4 a = A[q], b = B[q];
            sum += a.x * b.x + a.y * b.y + a.z * b.z + a.w * b.w;
        }
        #pragma unroll
        for (int o = 16; o; o >>= 1) sum += __shfl_down_sync(0xffffffffu, sum, o);
        if (lane == 0) {
            g_gram[i * (RDIM * RDIM) + r1 * RDIM + r2] = sum;
            g_gram[i * (RDIM * RDIM) + r2 * RDIM + r1] = sum;
        }
    }
}

// ============================================================================
// Caption word norms
// ============================================================================
__global__ void __launch_bounds__(256) ncap_kernel(const float* __restrict__ s) {
    const int gw = blockIdx.x * 8 + (threadIdx.x >> 5);
    const int lane = threadIdx.x & 31;
    const float4* row = (const float4*)(s + (size_t)gw * DDIM);
    float sum = 0.f;
    for (int q = lane; q < DDIM / 4; q += 32) {
        float4 a = row[q];
        sum += a.x * a.x + a.y * a.y + a.z * a.z + a.w * a.w;
    }
    #pragma unroll
    for (int o = 16; o; o >>= 1) sum += __shfl_down_sync(0xffffffffu, sum, o);
    if (lane == 0) g_ncap[gw] = sqrtf(sum);
}

// ============================================================================
// HMMA GEMM: C[4608][8192] = A[4608][1024]*B[8192][1024]^T (bf16 3-product)
// CTA 128x128, 8 warps (4x2), warp tile 32x64, K-chunk 32, double buffer.
// ============================================================================
#define PADK 40                          // bf16 per smem row (80 B stride, conflict-free)
#define ROWB (PADK * 2)                  // 80
#define TEN_BYTES (128 * ROWB)           // 10240 B per tensor tile
#define STAGE_BYTES (4 * TEN_BYTES)      // 40960 B
#define NCHUNK 32                        // 1024 / 32

__global__ void __launch_bounds__(256, 1) gemm_hmma() {
    extern __shared__ __align__(128) unsigned char dsm[];
    const int tid = threadIdx.x, wid = tid >> 5, lane = tid & 31;
    const int bx = blockIdx.x;  // N tile
    const int by = blockIdx.y;  // M tile
    const int wm = (wid & 3) * 32, wn = (wid >> 2) * 64;
    const int g = lane >> 2, tig = lane & 3;
    const unsigned sbase = su32(dsm);

    const char* gAh = (const char*)g_Ah + (size_t)by * 128 * 2048;
    const char* gAl = (const char*)g_Al + (size_t)by * 128 * 2048;
    const char* gBh = (const char*)g_Bh + (size_t)bx * 128 * 2048;
    const char* gBl = (const char*)g_Bl + (size_t)bx * 128 * 2048;

    float acc[2][8][4];
    #pragma unroll
    for (int mt = 0; mt < 2; ++mt)
        #pragma unroll
        for (int nt = 0; nt < 8; ++nt)
            #pragma unroll
            for (int q = 0; q < 4; ++q) acc[mt][nt][q] = 0.f;

    auto load_stage = [&](int c) {
        const unsigned tb = sbase + (unsigned)(c & 1) * STAGE_BYTES;
        const int kb = c * 64;  // byte offset within 2048B row
        #pragma unroll
        for (int it = 0; it < 8; ++it) {
            const char* gbase = (it < 2) ? gAh : (it < 4) ? gAl : (it < 6) ? gBh : gBl;
            const int ten = it >> 1;
            int rem = ((it & 1) << 8) + tid;       // 0..511
            int row = rem >> 2, q = rem & 3;
            cpa16_s(tb + ten * TEN_BYTES + row * ROWB + q * 16,
                    gbase + (size_t)row * 2048 + kb + q * 16);
        }
        cp_commit();
    };

    load_stage(0);
    load_stage(1);

    for (int c = 0; c < NCHUNK; ++c) {
        asm volatile("cp.async.wait_group 1;" ::: "memory");
        __syncthreads();

        const unsigned tb = sbase + (unsigned)(c & 1) * STAGE_BYTES;
        const unsigned AsH = tb, AsL = tb + TEN_BYTES;
        const unsigned BsH = tb + 2 * TEN_BYTES, BsL = tb + 3 * TEN_BYTES;

        #pragma unroll
        for (int kk = 0; kk < 2; ++kk) {
            const unsigned ka = (unsigned)(kk * 32 + 4 * tig);  // this thread's k byte offset

            unsigned ah[2][4], al[2][4];
            #pragma unroll
            for (int mt = 0; mt < 2; ++mt) {
                unsigned base = (unsigned)((wm + mt * 16 + g) * ROWB) + ka;
                ah[mt][0] = lds32(AsH + base);
                ah[mt][1] = lds32(AsH + base + 8 * ROWB);
                ah[mt][2] = lds32(AsH + base + 16);
                ah[mt][3] = lds32(AsH + base + 8 * ROWB + 16);
                al[mt][0] = lds32(AsL + base);
                al[mt][1] = lds32(AsL + base + 8 * ROWB);
                al[mt][2] = lds32(AsL + base + 16);
                al[mt][3] = lds32(AsL + base + 8 * ROWB + 16);
            }
            unsigned bh[8][2], bl[8][2];
            #pragma unroll
            for (int nb = 0; nb < 8; ++nb) {
                unsigned base = (unsigned)((wn + nb * 8 + g) * ROWB) + ka;
                bh[nb][0] = lds32(BsH + base);
                bh[nb][1] = lds32(BsH + base + 16);
                bl[nb][0] = lds32(BsL + base);
                bl[nb][1] = lds32(BsL + base + 16);
            }
            #pragma unroll
            for (int mt = 0; mt < 2; ++mt)
                #pragma unroll
                for (int nb = 0; nb < 8; ++nb) {
                    MMA16816(acc[mt][nb], ah[mt], bh[nb][0], bh[nb][1]);
                    MMA16816(acc[mt][nb], ah[mt], bl[nb][0], bl[nb][1]);
                    MMA16816(acc[mt][nb], al[mt], bh[nb][0], bh[nb][1]);
                }
        }
        __syncthreads();
        if (c + 2 < NCHUNK) load_stage(c + 2);
        else cp_commit();  // keep wait_group accounting uniform
    }

    // epilogue: acc -> g_C  (c0,c1 at row g; c2,c3 at row g+8; cols 2*tig)
    float* cbase = g_C + (size_t)(by * 128 + wm) * 8192 + bx * 128 + wn;
    #pragma unroll
    for (int mt = 0; mt < 2; ++mt)
        #pragma unroll
        for (int nb = 0; nb < 8; ++nb) {
            float* p0 = cbase + (size_t)(mt * 16 + g) * 8192 + nb * 8 + 2 * tig;
            *(float2*)p0 = make_float2(acc[mt][nb][0], acc[mt][nb][1]);
            *(float2*)(p0 + 8 * 8192) = make_float2(acc[mt][nb][2], acc[mt][nb][3]);
        }
}

// ============================================================================
// Per-pair epilogue -> scores[i][j]
// ============================================================================
__global__ void __launch_bounds__(64) scores_kernel(const int* __restrict__ s_l) {
    __shared__ float A0s[RDIM * 65];
    __shared__ float es [RDIM * 65];
    __shared__ float Gs [RDIM * RDIM];
    __shared__ float rn [RDIM];
    __shared__ float part[2];

    const int j = blockIdx.x, i = blockIdx.y;
    const int tid = threadIdx.x;
    const int L = s_l[j];

    const float* pc = g_C + (size_t)(i * RDIM) * 8192 + j * 64;
    for (int idx = tid; idx < RDIM * WDIM; idx += 64) {
        int r = idx >> 6, w = idx & 63;
        A0s[r * 65 + w] = pc[(size_t)r * 8192 + w];
    }
    const float* pg = g_gram + i * (RDIM * RDIM);
    for (int idx = tid; idx < RDIM * RDIM; idx += 64) Gs[idx] = pg[idx];
    __syncthreads();

    if (tid < RDIM) {
        float sum = 0.f;
        for (int w2 = 0; w2 < L; ++w2) {
            float x = A0s[tid * 65 + w2];
            x = (x > 0.f) ? x : 0.1f * x;
            sum += x * x;
        }
        rn[tid] = 9.0f / (sqrtf(sum) + 1e-8f);
    }
    __syncthreads();

    float t = 0.f;
    if (tid < L) {
        const int w = tid;
        float m = -1e30f;
        #pragma unroll
        for (int r = 0; r < RDIM; ++r) {
            float x = A0s[r * 65 + w];
            x = (x > 0.f) ? x : 0.1f * x;
            x *= rn[r];
            es[r * 65 + w] = x;
            m = fmaxf(m, x);
        }
        float se = 0.f, num = 0.f;
        #pragma unroll
        for (int r = 0; r < RDIM; ++r) {
            float e = __expf(es[r * 65 + w] - m);
            es[r * 65 + w] = e;
            se += e;
            num += e * A0s[r * 65 + w];
        }
        float quad = 0.f;
        #pragma unroll
        for (int r = 0; r < RDIM; ++r) {
            float er = es[r * 65 + w];
            float v = 0.5f * Gs[r * RDIM + r] * er;
            for (int r2 = r + 1; r2 < RDIM; ++r2) v += Gs[r * RDIM + r2] * es[r2 * 65 + w];
            quad += 2.0f * er * v;
        }
        quad = fmaxf(quad, 0.f);
        float nwei  = sqrtf(quad) / se;
        float numn  = num / se;
        float ncv   = g_ncap[j * WDIM + w];
        float denom = fmaxf(ncv * nwei, 1e-8f);
        float rowv  = numn / denom;
        t = __expf(6.0f * rowv);
    }
    #pragma unroll
    for (int o = 16; o; o >>= 1) t += __shfl_down_sync(0xffffffffu, t, o);
    if ((tid & 31) == 0) part[tid >> 5] = t;
    __syncthreads();
    if (tid == 0) g_scores[i * BDIM + j] = logf(part[0] + part[1]) / 6.0f;
}

// ============================================================================
// Hardest-negative hinge loss
// ============================================================================
__global__ void __launch_bounds__(128) loss_kernel(float* __restrict__ out) {
    __shared__ float red[128];
    const int t = threadIdx.x;
    const float di = g_scores[t * BDIM + t];
    float ms = 0.f, mi = 0.f;
    for (int k = 0; k < BDIM; ++k) {
        if (k == t) continue;
        ms = fmaxf(ms, fmaxf(0.f, 0.2f + g_scores[t * BDIM + k] - di));
        mi = fmaxf(mi, fmaxf(0.f, 0.2f + g_scores[k * BDIM + t] - di));
    }
    red[t] = ms + mi;
    __syncthreads();
    for (int st = 64; st > 0; st >>= 1) {
        if (t < st) red[t] += red[t + st];
        __syncthreads();
    }
    if (t == 0) out[0] = red[0];
}

// ============================================================================
extern "C" void kernel_launch(void* const* d_in, const int* in_sizes, int n_in,
                              void* d_out, int out_size) {
    const float* im = (const float*)d_in[0];
    const float* s  = (const float*)d_in[1];
    const int*   sl = (const int*)d_in[2];
    float* out = (float*)d_out;

    cudaFuncSetAttribute(gemm_hmma, cudaFuncAttributeMaxDynamicSharedMemorySize, 2 * STAGE_BYTES);

    convert_im_kernel<<<(BDIM * RDIM * DDIM / 4 + 255) / 256, 256>>>(im);
    convert_s_kernel<<<(BDIM * WDIM * DDIM / 4 + 255) / 256, 256>>>(s);
    gram_kernel<<<BDIM, 256>>>(im);
    ncap_kernel<<<(BDIM * WDIM) / 8, 256>>>(s);
    gemm_hmma<<<dim3(64, 36), 256, 2 * STAGE_BYTES>>>();
    scores_kernel<<<dim3(BDIM, BDIM), 64>>>(sl);
    loss_kernel<<<1, 128>>>(out);
}

// round 6
// speedup vs baseline: 3.3842x; 1.1309x over previous
#include <cuda_runtime.h>
#include <cuda_bf16.h>
#include <cstdint>
#include <math.h>

#define BDIM 128
#define RDIM 36
#define WDIM 64
#define DDIM 1024

// ---------------- device globals (no runtime allocation) ----------------
__device__ __align__(128) float g_C[(size_t)BDIM * RDIM * BDIM * WDIM];   // [4608][8192]
__device__ __align__(128) __nv_bfloat16 g_Ah[(size_t)BDIM * RDIM * DDIM];
__device__ __align__(128) __nv_bfloat16 g_Al[(size_t)BDIM * RDIM * DDIM];
__device__ __align__(128) __nv_bfloat16 g_Bh[(size_t)BDIM * WDIM * DDIM];
__device__ __align__(128) __nv_bfloat16 g_Bl[(size_t)BDIM * WDIM * DDIM];
__device__ float g_gram[BDIM * RDIM * RDIM];
__device__ float g_ncap[BDIM * WDIM];
__device__ float g_scores[BDIM * BDIM];

// ---------------- PTX helpers (baseline compute_103-safe only) ----------------
__device__ __forceinline__ unsigned su32(const void* p) {
    unsigned a;
    asm("{ .reg .u64 t; cvta.to.shared.u64 t, %1; cvt.u32.u64 %0, t; }" : "=r"(a) : "l"(p));
    return a;
}
__device__ __forceinline__ void cpa16_s(unsigned dst, const void* src) {
    asm volatile("cp.async.cg.shared.global [%0], [%1], 16;" :: "r"(dst), "l"(src));
}
__device__ __forceinline__ void cp_commit() { asm volatile("cp.async.commit_group;"); }
__device__ __forceinline__ unsigned lds32(unsigned addr) {
    unsigned v;
    asm volatile("ld.shared.b32 %0, [%1];" : "=r"(v) : "r"(addr));
    return v;
}

#define MMA16816(d, a, b0v, b1v) \
    asm volatile("mma.sync.aligned.m16n8k16.row.col.f32.bf16.bf16.f32 " \
                 "{%0,%1,%2,%3}, {%4,%5,%6,%7}, {%8,%9}, {%0,%1,%2,%3};" \
                 : "+f"((d)[0]), "+f"((d)[1]), "+f"((d)[2]), "+f"((d)[3]) \
                 : "r"((a)[0]), "r"((a)[1]), "r"((a)[2]), "r"((a)[3]), "r"(b0v), "r"(b1v))

// ============================================================================
// fp32 -> (hi, lo) bf16 split. Device globals referenced directly in device
// code (host-side symbol decay -> host shadow; GB300 ATS accepts it silently).
// ============================================================================
__device__ __forceinline__ void split_write(const float* __restrict__ src,
                                            __nv_bfloat16* __restrict__ hi,
                                            __nv_bfloat16* __restrict__ lo,
                                            int i) {
    float4 x = ((const float4*)src)[i];
    __nv_bfloat16 h0 = __float2bfloat16(x.x);
    __nv_bfloat16 h1 = __float2bfloat16(x.y);
    __nv_bfloat16 h2 = __float2bfloat16(x.z);
    __nv_bfloat16 h3 = __float2bfloat16(x.w);
    __nv_bfloat16 l0 = __float2bfloat16(x.x - __bfloat162float(h0));
    __nv_bfloat16 l1 = __float2bfloat16(x.y - __bfloat162float(h1));
    __nv_bfloat16 l2 = __float2bfloat16(x.z - __bfloat162float(h2));
    __nv_bfloat16 l3 = __float2bfloat16(x.w - __bfloat162float(h3));
    __nv_bfloat162* hp = (__nv_bfloat162*)hi;
    __nv_bfloat162* lp = (__nv_bfloat162*)lo;
    hp[2 * i]     = __nv_bfloat162(h0, h1);
    hp[2 * i + 1] = __nv_bfloat162(h2, h3);
    lp[2 * i]     = __nv_bfloat162(l0, l1);
    lp[2 * i + 1] = __nv_bfloat162(l2, l3);
}

__global__ void __launch_bounds__(256) convert_im_kernel(const float* __restrict__ im) {
    int i = blockIdx.x * 256 + threadIdx.x;
    if (i >= BDIM * RDIM * DDIM / 4) return;
    split_write(im, g_Ah, g_Al, i);
}

__global__ void __launch_bounds__(256) convert_s_kernel(const float* __restrict__ s) {
    int i = blockIdx.x * 256 + threadIdx.x;
    if (i >= BDIM * WDIM * DDIM / 4) return;
    split_write(s, g_Bh, g_Bl, i);
}

// ============================================================================
// Gram matrices (symmetric)
// ============================================================================
__global__ void __launch_bounds__(256) gram_kernel(const float* __restrict__ im) {
    const int i = blockIdx.x;
    const int warp = threadIdx.x >> 5, lane = threadIdx.x & 31;
    const float4* base = (const float4*)(im + (size_t)i * RDIM * DDIM);
    for (int p = warp; p < RDIM * RDIM; p += 8) {
        const int r1 = p / RDIM, r2 = p - r1 * RDIM;
        if (r1 > r2) continue;
        const float4* A = base + r1 * (DDIM / 4);
        const float4* B = base + r2 * (DDIM / 4);
        float sum = 0.f;
        for (int q = lane; q < DDIM / 4; q += 32) {
            float4 a = A[q], b = B[q];
            sum += a.x * b.x + a.y * b.y + a.z * b.z + a.w * b.w;
        }
        #pragma unroll
        for (int o = 16; o; o >>= 1) sum += __shfl_down_sync(0xffffffffu, sum, o);
        if (lane == 0) {
            g_gram[i * (RDIM * RDIM) + r1 * RDIM + r2] = sum;
            g_gram[i * (RDIM * RDIM) + r2 * RDIM + r1] = sum;
        }
    }
}

// ============================================================================
// Caption word norms
// ============================================================================
__global__ void __launch_bounds__(256) ncap_kernel(const float* __restrict__ s) {
    const int gw = blockIdx.x * 8 + (threadIdx.x >> 5);
    const int lane = threadIdx.x & 31;
    const float4* row = (const float4*)(s + (size_t)gw * DDIM);
    float sum = 0.f;
    for (int q = lane; q < DDIM / 4; q += 32) {
        float4 a = row[q];
        sum += a.x * a.x + a.y * a.y + a.z * a.z + a.w * a.w;
    }
    #pragma unroll
    for (int o = 16; o; o >>= 1) sum += __shfl_down_sync(0xffffffffu, sum, o);
    if (lane == 0) g_ncap[gw] = sqrtf(sum);
}

// ============================================================================
// HMMA GEMM: C[4608][8192] = A[4608][1024]*B[8192][1024]^T (bf16 3-product)
// CTA 128x128, 8 warps (4x2), warp tile 32x64, K-chunk 32, double buffer.
// 2 CTAs/SM (launch_bounds(256,2)): tensor pipe stays fed across barriers.
// B-fragments processed in two nb-halves to keep regs under 128.
// ============================================================================
#define PADK 40                          // bf16 per smem row (80 B stride, conflict-free)
#define ROWB (PADK * 2)                  // 80
#define TEN_BYTES (128 * ROWB)           // 10240 B per tensor tile
#define STAGE_BYTES (4 * TEN_BYTES)      // 40960 B
#define NCHUNK 32                        // 1024 / 32

__global__ void __launch_bounds__(256, 2) gemm_hmma() {
    extern __shared__ __align__(128) unsigned char dsm[];
    const int tid = threadIdx.x, wid = tid >> 5, lane = tid & 31;
    const int bx = blockIdx.x;  // N tile
    const int by = blockIdx.y;  // M tile
    const int wm = (wid & 3) * 32, wn = (wid >> 2) * 64;
    const int g = lane >> 2, tig = lane & 3;
    const unsigned sbase = su32(dsm);

    const char* gAh = (const char*)g_Ah + (size_t)by * 128 * 2048;
    const char* gAl = (const char*)g_Al + (size_t)by * 128 * 2048;
    const char* gBh = (const char*)g_Bh + (size_t)bx * 128 * 2048;
    const char* gBl = (const char*)g_Bl + (size_t)bx * 128 * 2048;

    float acc[2][8][4];
    #pragma unroll
    for (int mt = 0; mt < 2; ++mt)
        #pragma unroll
        for (int nt = 0; nt < 8; ++nt)
            #pragma unroll
            for (int q = 0; q < 4; ++q) acc[mt][nt][q] = 0.f;

    auto load_stage = [&](int c) {
        const unsigned tb = sbase + (unsigned)(c & 1) * STAGE_BYTES;
        const int kb = c * 64;  // byte offset within 2048B row
        #pragma unroll
        for (int it = 0; it < 8; ++it) {
            const char* gbase = (it < 2) ? gAh : (it < 4) ? gAl : (it < 6) ? gBh : gBl;
            const int ten = it >> 1;
            int rem = ((it & 1) << 8) + tid;       // 0..511
            int row = rem >> 2, q = rem & 3;
            cpa16_s(tb + ten * TEN_BYTES + row * ROWB + q * 16,
                    gbase + (size_t)row * 2048 + kb + q * 16);
        }
        cp_commit();
    };

    load_stage(0);
    load_stage(1);

    for (int c = 0; c < NCHUNK; ++c) {
        asm volatile("cp.async.wait_group 1;" ::: "memory");
        __syncthreads();

        const unsigned tb = sbase + (unsigned)(c & 1) * STAGE_BYTES;
        const unsigned AsH = tb, AsL = tb + TEN_BYTES;
        const unsigned BsH = tb + 2 * TEN_BYTES, BsL = tb + 3 * TEN_BYTES;

        #pragma unroll
        for (int kk = 0; kk < 2; ++kk) {
            const unsigned ka = (unsigned)(kk * 32 + 4 * tig);

            unsigned ah[2][4], al[2][4];
            #pragma unroll
            for (int mt = 0; mt < 2; ++mt) {
                unsigned base = (unsigned)((wm + mt * 16 + g) * ROWB) + ka;
                ah[mt][0] = lds32(AsH + base);
                ah[mt][1] = lds32(AsH + base + 8 * ROWB);
                ah[mt][2] = lds32(AsH + base + 16);
                ah[mt][3] = lds32(AsH + base + 8 * ROWB + 16);
                al[mt][0] = lds32(AsL + base);
                al[mt][1] = lds32(AsL + base + 8 * ROWB);
                al[mt][2] = lds32(AsL + base + 16);
                al[mt][3] = lds32(AsL + base + 8 * ROWB + 16);
            }
            // two halves of 4 nb each: keeps B fragment registers at 16
            #pragma unroll
            for (int h = 0; h < 2; ++h) {
                unsigned bh[4][2], bl[4][2];
                #pragma unroll
                for (int q = 0; q < 4; ++q) {
                    int nb = h * 4 + q;
                    unsigned base = (unsigned)((wn + nb * 8 + g) * ROWB) + ka;
                    bh[q][0] = lds32(BsH + base);
                    bh[q][1] = lds32(BsH + base + 16);
                    bl[q][0] = lds32(BsL + base);
                    bl[q][1] = lds32(BsL + base + 16);
                }
                #pragma unroll
                for (int mt = 0; mt < 2; ++mt)
                    #pragma unroll
                    for (int q = 0; q < 4; ++q) {
                        int nb = h * 4 + q;
                        MMA16816(acc[mt][nb], ah[mt], bh[q][0], bh[q][1]);
                        MMA16816(acc[mt][nb], ah[mt], bl[q][0], bl[q][1]);
                        MMA16816(acc[mt][nb], al[mt], bh[q][0], bh[q][1]);
                    }
            }
        }
        __syncthreads();
        if (c + 2 < NCHUNK) load_stage(c + 2);
        else cp_commit();  // keep wait_group accounting uniform
    }

    // epilogue: acc -> g_C
    float* cbase = g_C + (size_t)(by * 128 + wm) * 8192 + bx * 128 + wn;
    #pragma unroll
    for (int mt = 0; mt < 2; ++mt)
        #pragma unroll
        for (int nb = 0; nb < 8; ++nb) {
            float* p0 = cbase + (size_t)(mt * 16 + g) * 8192 + nb * 8 + 2 * tig;
            *(float2*)p0 = make_float2(acc[mt][nb][0], acc[mt][nb][1]);
            *(float2*)(p0 + 8 * 8192) = make_float2(acc[mt][nb][2], acc[mt][nb][3]);
        }
}

// ============================================================================
// Per-pair epilogue -> scores[i][j]. Softmax weights register-resident;
// Gram read as broadcast float4 (G row stride 144B, 16B-aligned).
// ============================================================================
__global__ void __launch_bounds__(64) scores_kernel(const int* __restrict__ s_l) {
    __shared__ float A0s[RDIM * 65];
    __shared__ float Gs [RDIM * RDIM];   // row stride 36 floats = 144 B (16B-aligned)
    __shared__ float rn [RDIM];
    __shared__ float part[2];

    const int j = blockIdx.x, i = blockIdx.y;
    const int tid = threadIdx.x;
    const int L = s_l[j];

    const float* pc = g_C + (size_t)(i * RDIM) * 8192 + j * 64;
    for (int idx = tid; idx < RDIM * WDIM; idx += 64) {
        int r = idx >> 6, w = idx & 63;
        A0s[r * 65 + w] = pc[(size_t)r * 8192 + w];
    }
    const float* pg = g_gram + i * (RDIM * RDIM);
    for (int idx = tid; idx < RDIM * RDIM; idx += 64) Gs[idx] = pg[idx];
    __syncthreads();

    if (tid < RDIM) {
        float sum = 0.f;
        for (int w2 = 0; w2 < L; ++w2) {
            float x = A0s[tid * 65 + w2];
            x = (x > 0.f) ? x : 0.1f * x;
            sum += x * x;
        }
        rn[tid] = 9.0f / (sqrtf(sum) + 1e-8f);
    }
    __syncthreads();

    float t = 0.f;
    if (tid < L) {
        const int w = tid;
        float e[RDIM];          // register-resident
        float m = -1e30f;
        #pragma unroll
        for (int r = 0; r < RDIM; ++r) {
            float x = A0s[r * 65 + w];
            x = (x > 0.f) ? x : 0.1f * x;
            x *= rn[r];
            e[r] = x;
            m = fmaxf(m, x);
        }
        float se = 0.f, num = 0.f;
        #pragma unroll
        for (int r = 0; r < RDIM; ++r) {
            float ev = __expf(e[r] - m);
            e[r] = ev;
            se += ev;
            num += ev * A0s[r * 65 + w];
        }
        // quad = e^T G e : G broadcast via float4, e in registers
        float quad = 0.f;
        #pragma unroll
        for (int r = 0; r < RDIM; ++r) {
            const float4* gr = (const float4*)(Gs + r * RDIM);
            float v = 0.f;
            #pragma unroll
            for (int q = 0; q < RDIM / 4; ++q) {
                float4 gv = gr[q];
                v += gv.x * e[4 * q] + gv.y * e[4 * q + 1]
                   + gv.z * e[4 * q + 2] + gv.w * e[4 * q + 3];
            }
            quad += e[r] * v;
        }
        quad = fmaxf(quad, 0.f);
        float nwei  = sqrtf(quad) / se;
        float numn  = num / se;
        float ncv   = g_ncap[j * WDIM + w];
        float denom = fmaxf(ncv * nwei, 1e-8f);
        float rowv  = numn / denom;
        t = __expf(6.0f * rowv);
    }
    #pragma unroll
    for (int o = 16; o; o >>= 1) t += __shfl_down_sync(0xffffffffu, t, o);
    if ((tid & 31) == 0) part[tid >> 5] = t;
    __syncthreads();
    if (tid == 0) g_scores[i * BDIM + j] = logf(part[0] + part[1]) / 6.0f;
}

// ============================================================================
// Hardest-negative hinge loss
// ============================================================================
__global__ void __launch_bounds__(128) loss_kernel(float* __restrict__ out) {
    __shared__ float red[128];
    const int t = threadIdx.x;
    const float di = g_scores[t * BDIM + t];
    float ms = 0.f, mi = 0.f;
    for (int k = 0; k < BDIM; ++k) {
        if (k == t) continue;
        ms = fmaxf(ms, fmaxf(0.f, 0.2f + g_scores[t * BDIM + k] - di));
        mi = fmaxf(mi, fmaxf(0.f, 0.2f + g_scores[k * BDIM + t] - di));
    }
    red[t] = ms + mi;
    __syncthreads();
    for (int st = 64; st > 0; st >>= 1) {
        if (t < st) red[t] += red[t + st];
        __syncthreads();
    }
    if (t == 0) out[0] = red[0];
}

// ============================================================================
extern "C" void kernel_launch(void* const* d_in, const int* in_sizes, int n_in,
                              void* d_out, int out_size) {
    const float* im = (const float*)d_in[0];
    const float* s  = (const float*)d_in[1];
    const int*   sl = (const int*)d_in[2];
    float* out = (float*)d_out;

    cudaFuncSetAttribute(gemm_hmma, cudaFuncAttributeMaxDynamicSharedMemorySize, 2 * STAGE_BYTES);

    convert_im_kernel<<<(BDIM * RDIM * DDIM / 4 + 255) / 256, 256>>>(im);
    convert_s_kernel<<<(BDIM * WDIM * DDIM / 4 + 255) / 256, 256>>>(s);
    gram_kernel<<<BDIM, 256>>>(im);
    ncap_kernel<<<(BDIM * WDIM) / 8, 256>>>(s);
    gemm_hmma<<<dim3(64, 36), 256, 2 * STAGE_BYTES>>>();
    scores_kernel<<<dim3(BDIM, BDIM), 64>>>(sl);
    loss_kernel<<<1, 128>>>(out);
}

// round 7
// speedup vs baseline: 4.3252x; 1.2780x over previous
#include <cuda_runtime.h>
#include <cuda_bf16.h>
#include <cuda_fp16.h>
#include <cstdint>
#include <math.h>

#define BDIM 128
#define RDIM 36
#define WDIM 64
#define DDIM 1024

// ---------------- device globals (no runtime allocation) ----------------
__device__ __align__(128) float g_C[(size_t)BDIM * RDIM * BDIM * WDIM];   // [4608][8192]
__device__ __align__(128) __half g_A [(size_t)BDIM * RDIM * DDIM];        // fp16(im), hi only
__device__ __align__(128) __half g_Bh[(size_t)BDIM * WDIM * DDIM];        // fp16 split of s
__device__ __align__(128) __half g_Bl[(size_t)BDIM * WDIM * DDIM];
__device__ float g_gram[BDIM * RDIM * RDIM];
__device__ float g_ncap[BDIM * WDIM];
__device__ float g_scores[BDIM * BDIM];

// ---------------- PTX helpers (baseline compute_103-safe only) ----------------
__device__ __forceinline__ unsigned su32(const void* p) {
    unsigned a;
    asm("{ .reg .u64 t; cvta.to.shared.u64 t, %1; cvt.u32.u64 %0, t; }" : "=r"(a) : "l"(p));
    return a;
}
__device__ __forceinline__ void cpa16_s(unsigned dst, const void* src) {
    asm volatile("cp.async.cg.shared.global [%0], [%1], 16;" :: "r"(dst), "l"(src));
}
__device__ __forceinline__ void cp_commit() { asm volatile("cp.async.commit_group;"); }
__device__ __forceinline__ unsigned lds32(unsigned addr) {
    unsigned v;
    asm volatile("ld.shared.b32 %0, [%1];" : "=r"(v) : "r"(addr));
    return v;
}

#define MMAF16(d, a, b0v, b1v) \
    asm volatile("mma.sync.aligned.m16n8k16.row.col.f32.f16.f16.f32 " \
                 "{%0,%1,%2,%3}, {%4,%5,%6,%7}, {%8,%9}, {%0,%1,%2,%3};" \
                 : "+f"((d)[0]), "+f"((d)[1]), "+f"((d)[2]), "+f"((d)[3]) \
                 : "r"((a)[0]), "r"((a)[1]), "r"((a)[2]), "r"((a)[3]), "r"(b0v), "r"(b1v))

// ============================================================================
// Converts. Device globals referenced DIRECTLY in device code (host-side
// symbol decay -> host shadow; GB300 ATS accepts it silently — R3/R4 bug).
// ============================================================================
__global__ void __launch_bounds__(256) convert_im_kernel(const float* __restrict__ im) {
    int i = blockIdx.x * 256 + threadIdx.x;                 // over float4s
    if (i >= BDIM * RDIM * DDIM / 4) return;
    float4 x = ((const float4*)im)[i];
    __half2* ap = (__half2*)g_A;
    ap[2 * i]     = __half2(__float2half_rn(x.x), __float2half_rn(x.y));
    ap[2 * i + 1] = __half2(__float2half_rn(x.z), __float2half_rn(x.w));
}

__global__ void __launch_bounds__(256) convert_s_kernel(const float* __restrict__ s) {
    int i = blockIdx.x * 256 + threadIdx.x;
    if (i >= BDIM * WDIM * DDIM / 4) return;
    float4 x = ((const float4*)s)[i];
    __half h0 = __float2half_rn(x.x);
    __half h1 = __float2half_rn(x.y);
    __half h2 = __float2half_rn(x.z);
    __half h3 = __float2half_rn(x.w);
    __half l0 = __float2half_rn(x.x - __half2float(h0));
    __half l1 = __float2half_rn(x.y - __half2float(h1));
    __half l2 = __float2half_rn(x.z - __half2float(h2));
    __half l3 = __float2half_rn(x.w - __half2float(h3));
    __half2* hp = (__half2*)g_Bh;
    __half2* lp = (__half2*)g_Bl;
    hp[2 * i]     = __half2(h0, h1);
    hp[2 * i + 1] = __half2(h2, h3);
    lp[2 * i]     = __half2(l0, l1);
    lp[2 * i + 1] = __half2(l2, l3);
}

// ============================================================================
// Gram matrices (symmetric)
// ============================================================================
__global__ void __launch_bounds__(256) gram_kernel(const float* __restrict__ im) {
    const int i = blockIdx.x;
    const int warp = threadIdx.x >> 5, lane = threadIdx.x & 31;
    const float4* base = (const float4*)(im + (size_t)i * RDIM * DDIM);
    for (int p = warp; p < RDIM * RDIM; p += 8) {
        const int r1 = p / RDIM, r2 = p - r1 * RDIM;
        if (r1 > r2) continue;
        const float4* A = base + r1 * (DDIM / 4);
        const float4* B = base + r2 * (DDIM / 4);
        float sum = 0.f;
        for (int q = lane; q < DDIM / 4; q += 32) {
            float4 a = A[q], b = B[q];
            sum += a.x * b.x + a.y * b.y + a.z * b.z + a.w * b.w;
        }
        #pragma unroll
        for (int o = 16; o; o >>= 1) sum += __shfl_down_sync(0xffffffffu, sum, o);
        if (lane == 0) {
            g_gram[i * (RDIM * RDIM) + r1 * RDIM + r2] = sum;
            g_gram[i * (RDIM * RDIM) + r2 * RDIM + r1] = sum;
        }
    }
}

// ============================================================================
// Caption word norms
// ============================================================================
__global__ void __launch_bounds__(256) ncap_kernel(const float* __restrict__ s) {
    const int gw = blockIdx.x * 8 + (threadIdx.x >> 5);
    const int lane = threadIdx.x & 31;
    const float4* row = (const float4*)(s + (size_t)gw * DDIM);
    float sum = 0.f;
    for (int q = lane; q < DDIM / 4; q += 32) {
        float4 a = row[q];
        sum += a.x * a.x + a.y * a.y + a.z * a.z + a.w * a.w;
    }
    #pragma unroll
    for (int o = 16; o; o >>= 1) sum += __shfl_down_sync(0xffffffffu, sum, o);
    if (lane == 0) g_ncap[gw] = sqrtf(sum);
}

// ============================================================================
// HMMA GEMM (fp16 2-product): C = A_h * (B_h + B_l)
// CTA 128x128, 8 warps (4x2), warp tile 32x64, K-chunk 32, double buffer,
// 2 CTAs/SM. 3 tensors per stage (A, Bh, Bl) -> 24 KB/stage.
// ============================================================================
#define PADK 40                          // fp16 per smem row (80 B stride, conflict-free)
#define ROWB (PADK * 2)                  // 80
#define TEN_BYTES (128 * ROWB)           // 10240 B per tensor tile
#define STAGE_BYTES (3 * TEN_BYTES)      // 30720 B
#define NCHUNK 32                        // 1024 / 32

__global__ void __launch_bounds__(256, 2) gemm_hmma() {
    extern __shared__ __align__(128) unsigned char dsm[];
    const int tid = threadIdx.x, wid = tid >> 5, lane = tid & 31;
    const int bx = blockIdx.x;  // N tile
    const int by = blockIdx.y;  // M tile
    const int wm = (wid & 3) * 32, wn = (wid >> 2) * 64;
    const int g = lane >> 2, tig = lane & 3;
    const unsigned sbase = su32(dsm);

    const char* gA  = (const char*)g_A  + (size_t)by * 128 * 2048;
    const char* gBh = (const char*)g_Bh + (size_t)bx * 128 * 2048;
    const char* gBl = (const char*)g_Bl + (size_t)bx * 128 * 2048;

    float acc[2][8][4];
    #pragma unroll
    for (int mt = 0; mt < 2; ++mt)
        #pragma unroll
        for (int nt = 0; nt < 8; ++nt)
            #pragma unroll
            for (int q = 0; q < 4; ++q) acc[mt][nt][q] = 0.f;

    auto load_stage = [&](int c) {
        const unsigned tb = sbase + (unsigned)(c & 1) * STAGE_BYTES;
        const int kb = c * 64;  // byte offset within 2048B row
        #pragma unroll
        for (int it = 0; it < 6; ++it) {
            const char* gbase = (it < 2) ? gA : (it < 4) ? gBh : gBl;
            const int ten = it >> 1;
            int rem = ((it & 1) << 8) + tid;       // 0..511
            int row = rem >> 2, q = rem & 3;
            cpa16_s(tb + ten * TEN_BYTES + row * ROWB + q * 16,
                    gbase + (size_t)row * 2048 + kb + q * 16);
        }
        cp_commit();
    };

    load_stage(0);
    load_stage(1);

    for (int c = 0; c < NCHUNK; ++c) {
        asm volatile("cp.async.wait_group 1;" ::: "memory");
        __syncthreads();

        const unsigned tb = sbase + (unsigned)(c & 1) * STAGE_BYTES;
        const unsigned As = tb, BsH = tb + TEN_BYTES, BsL = tb + 2 * TEN_BYTES;

        #pragma unroll
        for (int kk = 0; kk < 2; ++kk) {
            const unsigned ka = (unsigned)(kk * 32 + 4 * tig);

            unsigned a[2][4];
            #pragma unroll
            for (int mt = 0; mt < 2; ++mt) {
                unsigned base = (unsigned)((wm + mt * 16 + g) * ROWB) + ka;
                a[mt][0] = lds32(As + base);
                a[mt][1] = lds32(As + base + 8 * ROWB);
                a[mt][2] = lds32(As + base + 16);
                a[mt][3] = lds32(As + base + 8 * ROWB + 16);
            }
            // two halves of 4 nb each: caps B fragment registers
            #pragma unroll
            for (int h = 0; h < 2; ++h) {
                unsigned bh[4][2], bl[4][2];
                #pragma unroll
                for (int q = 0; q < 4; ++q) {
                    int nb = h * 4 + q;
                    unsigned base = (unsigned)((wn + nb * 8 + g) * ROWB) + ka;
                    bh[q][0] = lds32(BsH + base);
                    bh[q][1] = lds32(BsH + base + 16);
                    bl[q][0] = lds32(BsL + base);
                    bl[q][1] = lds32(BsL + base + 16);
                }
                #pragma unroll
                for (int mt = 0; mt < 2; ++mt)
                    #pragma unroll
                    for (int q = 0; q < 4; ++q) {
                        int nb = h * 4 + q;
                        MMAF16(acc[mt][nb], a[mt], bh[q][0], bh[q][1]);
                        MMAF16(acc[mt][nb], a[mt], bl[q][0], bl[q][1]);
                    }
            }
        }
        __syncthreads();
        if (c + 2 < NCHUNK) load_stage(c + 2);
        else cp_commit();  // keep wait_group accounting uniform
    }

    // epilogue: acc -> g_C
    float* cbase = g_C + (size_t)(by * 128 + wm) * 8192 + bx * 128 + wn;
    #pragma unroll
    for (int mt = 0; mt < 2; ++mt)
        #pragma unroll
        for (int nb = 0; nb < 8; ++nb) {
            float* p0 = cbase + (size_t)(mt * 16 + g) * 8192 + nb * 8 + 2 * tig;
            *(float2*)p0 = make_float2(acc[mt][nb][0], acc[mt][nb][1]);
            *(float2*)(p0 + 8 * 8192) = make_float2(acc[mt][nb][2], acc[mt][nb][3]);
        }
}

// ============================================================================
// Per-pair epilogue -> scores[i][j]. Softmax weights register-resident;
// Gram read as broadcast float4.
// ============================================================================
__global__ void __launch_bounds__(64) scores_kernel(const int* __restrict__ s_l) {
    __shared__ float A0s[RDIM * 65];
    __shared__ float Gs [RDIM * RDIM];
    __shared__ float rn [RDIM];
    __shared__ float part[2];

    const int j = blockIdx.x, i = blockIdx.y;
    const int tid = threadIdx.x;
    const int L = s_l[j];

    const float* pc = g_C + (size_t)(i * RDIM) * 8192 + j * 64;
    for (int idx = tid; idx < RDIM * WDIM; idx += 64) {
        int r = idx >> 6, w = idx & 63;
        A0s[r * 65 + w] = pc[(size_t)r * 8192 + w];
    }
    const float* pg = g_gram + i * (RDIM * RDIM);
    for (int idx = tid; idx < RDIM * RDIM; idx += 64) Gs[idx] = pg[idx];
    __syncthreads();

    if (tid < RDIM) {
        float sum = 0.f;
        for (int w2 = 0; w2 < L; ++w2) {
            float x = A0s[tid * 65 + w2];
            x = (x > 0.f) ? x : 0.1f * x;
            sum += x * x;
        }
        rn[tid] = 9.0f / (sqrtf(sum) + 1e-8f);
    }
    __syncthreads();

    float t = 0.f;
    if (tid < L) {
        const int w = tid;
        float e[RDIM];
        float m = -1e30f;
        #pragma unroll
        for (int r = 0; r < RDIM; ++r) {
            float x = A0s[r * 65 + w];
            x = (x > 0.f) ? x : 0.1f * x;
            x *= rn[r];
            e[r] = x;
            m = fmaxf(m, x);
        }
        float se = 0.f, num = 0.f;
        #pragma unroll
        for (int r = 0; r < RDIM; ++r) {
            float ev = __expf(e[r] - m);
            e[r] = ev;
            se += ev;
            num += ev * A0s[r * 65 + w];
        }
        float quad = 0.f;
        #pragma unroll
        for (int r = 0; r < RDIM; ++r) {
            const float4* gr = (const float4*)(Gs + r * RDIM);
            float v = 0.f;
            #pragma unroll
            for (int q = 0; q < RDIM / 4; ++q) {
                float4 gv = gr[q];
                v += gv.x * e[4 * q] + gv.y * e[4 * q + 1]
                   + gv.z * e[4 * q + 2] + gv.w * e[4 * q + 3];
            }
            quad += e[r] * v;
        }
        quad = fmaxf(quad, 0.f);
        float nwei  = sqrtf(quad) / se;
        float numn  = num / se;
        float ncv   = g_ncap[j * WDIM + w];
        float denom = fmaxf(ncv * nwei, 1e-8f);
        float rowv  = numn / denom;
        t = __expf(6.0f * rowv);
    }
    #pragma unroll
    for (int o = 16; o; o >>= 1) t += __shfl_down_sync(0xffffffffu, t, o);
    if ((tid & 31) == 0) part[tid >> 5] = t;
    __syncthreads();
    if (tid == 0) g_scores[i * BDIM + j] = logf(part[0] + part[1]) / 6.0f;
}

// ============================================================================
// Hardest-negative hinge loss
// ============================================================================
__global__ void __launch_bounds__(128) loss_kernel(float* __restrict__ out) {
    __shared__ float red[128];
    const int t = threadIdx.x;
    const float di = g_scores[t * BDIM + t];
    float ms = 0.f, mi = 0.f;
    for (int k = 0; k < BDIM; ++k) {
        if (k == t) continue;
        ms = fmaxf(ms, fmaxf(0.f, 0.2f + g_scores[t * BDIM + k] - di));
        mi = fmaxf(mi, fmaxf(0.f, 0.2f + g_scores[k * BDIM + t] - di));
    }
    red[t] = ms + mi;
    __syncthreads();
    for (int st = 64; st > 0; st >>= 1) {
        if (t < st) red[t] += red[t + st];
        __syncthreads();
    }
    if (t == 0) out[0] = red[0];
}

// ============================================================================
extern "C" void kernel_launch(void* const* d_in, const int* in_sizes, int n_in,
                              void* d_out, int out_size) {
    const float* im = (const float*)d_in[0];
    const float* s  = (const float*)d_in[1];
    const int*   sl = (const int*)d_in[2];
    float* out = (float*)d_out;

    cudaFuncSetAttribute(gemm_hmma, cudaFuncAttributeMaxDynamicSharedMemorySize, 2 * STAGE_BYTES);

    convert_im_kernel<<<(BDIM * RDIM * DDIM / 4 + 255) / 256, 256>>>(im);
    convert_s_kernel<<<(BDIM * WDIM * DDIM / 4 + 255) / 256, 256>>>(s);
    gram_kernel<<<BDIM, 256>>>(im);
    ncap_kernel<<<(BDIM * WDIM) / 8, 256>>>(s);
    gemm_hmma<<<dim3(64, 36), 256, 2 * STAGE_BYTES>>>();
    scores_kernel<<<dim3(BDIM, BDIM), 64>>>(sl);
    loss_kernel<<<1, 128>>>(out);
}

// round 8
// speedup vs baseline: 6.2802x; 1.4520x over previous
#include <cuda_runtime.h>
#include <cuda_fp16.h>
#include <cstdint>
#include <math.h>

#define BDIM 128
#define RDIM 36
#define WDIM 64
#define DDIM 1024

// ---------------- device globals (no runtime allocation) ----------------
__device__ __align__(128) float g_C[(size_t)BDIM * RDIM * BDIM * WDIM];   // [4608][8192]
__device__ __align__(128) __half g_A[(size_t)BDIM * RDIM * DDIM];         // fp16(im)
__device__ __align__(128) __half g_B[(size_t)BDIM * WDIM * DDIM];         // fp16(s)
__device__ float g_gram[BDIM * RDIM * RDIM];
__device__ float g_ncap[BDIM * WDIM];
__device__ float g_scores[BDIM * BDIM];

// ---------------- PTX helpers (baseline compute_103-safe only) ----------------
__device__ __forceinline__ unsigned su32(const void* p) {
    unsigned a;
    asm("{ .reg .u64 t; cvta.to.shared.u64 t, %1; cvt.u32.u64 %0, t; }" : "=r"(a) : "l"(p));
    return a;
}
__device__ __forceinline__ void cpa16_s(unsigned dst, const void* src) {
    asm volatile("cp.async.cg.shared.global [%0], [%1], 16;" :: "r"(dst), "l"(src));
}
__device__ __forceinline__ void cp_commit() { asm volatile("cp.async.commit_group;"); }
__device__ __forceinline__ unsigned lds32(unsigned addr) {
    unsigned v;
    asm volatile("ld.shared.b32 %0, [%1];" : "=r"(v) : "r"(addr));
    return v;
}

#define MMAF16(d, a, b0v, b1v) \
    asm volatile("mma.sync.aligned.m16n8k16.row.col.f32.f16.f16.f32 " \
                 "{%0,%1,%2,%3}, {%4,%5,%6,%7}, {%8,%9}, {%0,%1,%2,%3};" \
                 : "+f"((d)[0]), "+f"((d)[1]), "+f"((d)[2]), "+f"((d)[3]) \
                 : "r"((a)[0]), "r"((a)[1]), "r"((a)[2]), "r"((a)[3]), "r"(b0v), "r"(b1v))

// ============================================================================
// Converts. Device globals referenced DIRECTLY in device code (host-side
// symbol decay -> host shadow; GB300 ATS accepts it silently).
// ============================================================================
__global__ void __launch_bounds__(256) convert_im_kernel(const float* __restrict__ im) {
    int i = blockIdx.x * 256 + threadIdx.x;                 // over float4s
    if (i >= BDIM * RDIM * DDIM / 4) return;
    float4 x = ((const float4*)im)[i];
    __half2* ap = (__half2*)g_A;
    ap[2 * i]     = __half2(__float2half_rn(x.x), __float2half_rn(x.y));
    ap[2 * i + 1] = __half2(__float2half_rn(x.z), __float2half_rn(x.w));
}

__global__ void __launch_bounds__(256) convert_s_kernel(const float* __restrict__ s) {
    int i = blockIdx.x * 256 + threadIdx.x;
    if (i >= BDIM * WDIM * DDIM / 4) return;
    float4 x = ((const float4*)s)[i];
    __half2* bp = (__half2*)g_B;
    bp[2 * i]     = __half2(__float2half_rn(x.x), __float2half_rn(x.y));
    bp[2 * i + 1] = __half2(__float2half_rn(x.z), __float2half_rn(x.w));
}

// ============================================================================
// Gram matrices (symmetric)
// ============================================================================
__global__ void __launch_bounds__(256) gram_kernel(const float* __restrict__ im) {
    const int i = blockIdx.x;
    const int warp = threadIdx.x >> 5, lane = threadIdx.x & 31;
    const float4* base = (const float4*)(im + (size_t)i * RDIM * DDIM);
    for (int p = warp; p < RDIM * RDIM; p += 8) {
        const int r1 = p / RDIM, r2 = p - r1 * RDIM;
        if (r1 > r2) continue;
        const float4* A = base + r1 * (DDIM / 4);
        const float4* B = base + r2 * (DDIM / 4);
        float sum = 0.f;
        for (int q = lane; q < DDIM / 4; q += 32) {
            float4 a = A[q], b = B[q];
            sum += a.x * b.x + a.y * b.y + a.z * b.z + a.w * b.w;
        }
        #pragma unroll
        for (int o = 16; o; o >>= 1) sum += __shfl_down_sync(0xffffffffu, sum, o);
        if (lane == 0) {
            g_gram[i * (RDIM * RDIM) + r1 * RDIM + r2] = sum;
            g_gram[i * (RDIM * RDIM) + r2 * RDIM + r1] = sum;
        }
    }
}

// ============================================================================
// Caption word norms
// ============================================================================
__global__ void __launch_bounds__(256) ncap_kernel(const float* __restrict__ s) {
    const int gw = blockIdx.x * 8 + (threadIdx.x >> 5);
    const int lane = threadIdx.x & 31;
    const float4* row = (const float4*)(s + (size_t)gw * DDIM);
    float sum = 0.f;
    for (int q = lane; q < DDIM / 4; q += 32) {
        float4 a = row[q];
        sum += a.x * a.x + a.y * a.y + a.z * a.z + a.w * a.w;
    }
    #pragma unroll
    for (int o = 16; o; o >>= 1) sum += __shfl_down_sync(0xffffffffu, sum, o);
    if (lane == 0) g_ncap[gw] = sqrtf(sum);
}

// ============================================================================
// HMMA GEMM (pure fp16): C = fp16(A) * fp16(B)^T, fp32 accumulate
// CTA 128x128, 8 warps (4x2), warp tile 32x64, K-chunk 64, 3-stage pipeline,
// 2 CTAs/SM.
// ============================================================================
#define ROWB 144                         // 64 fp16 = 128 B + 16 B pad (conflict-free)
#define TEN_BYTES (128 * ROWB)           // 18432 B per tensor tile
#define STAGE_BYTES (2 * TEN_BYTES)      // 36864 B
#define NSTAGES 3
#define NCHUNK 16                        // 1024 / 64

__global__ void __launch_bounds__(256, 2) gemm_hmma() {
    extern __shared__ __align__(128) unsigned char dsm[];
    const int tid = threadIdx.x, wid = tid >> 5, lane = tid & 31;
    const int bx = blockIdx.x;  // N tile
    const int by = blockIdx.y;  // M tile
    const int wm = (wid & 3) * 32, wn = (wid >> 2) * 64;
    const int g = lane >> 2, tig = lane & 3;
    const unsigned sbase = su32(dsm);

    const char* gA = (const char*)g_A + (size_t)by * 128 * 2048;
    const char* gB = (const char*)g_B + (size_t)bx * 128 * 2048;

    float acc[2][8][4];
    #pragma unroll
    for (int mt = 0; mt < 2; ++mt)
        #pragma unroll
        for (int nt = 0; nt < 8; ++nt)
            #pragma unroll
            for (int q = 0; q < 4; ++q) acc[mt][nt][q] = 0.f;

    auto load_stage = [&](int c) {
        const unsigned tb = sbase + (unsigned)(c % NSTAGES) * STAGE_BYTES;
        const int kb = c * 128;  // byte offset within 2048B row
        #pragma unroll
        for (int it = 0; it < 8; ++it) {
            int idx = it * 256 + tid;            // 0..2047
            const char* gbase = (idx < 1024) ? gA : gB;
            int ten = idx >> 10;
            int rem = idx & 1023;
            int row = rem >> 3, q = rem & 7;
            cpa16_s(tb + ten * TEN_BYTES + row * ROWB + q * 16,
                    gbase + (size_t)row * 2048 + kb + q * 16);
        }
        cp_commit();
    };

    load_stage(0);
    load_stage(1);
    load_stage(2);

    for (int c = 0; c < NCHUNK; ++c) {
        asm volatile("cp.async.wait_group 2;" ::: "memory");
        __syncthreads();

        const unsigned tb = sbase + (unsigned)(c % NSTAGES) * STAGE_BYTES;
        const unsigned As = tb, Bs = tb + TEN_BYTES;

        #pragma unroll
        for (int kk = 0; kk < 4; ++kk) {
            const unsigned ka = (unsigned)(kk * 32 + 4 * tig);

            unsigned a[2][4];
            #pragma unroll
            for (int mt = 0; mt < 2; ++mt) {
                unsigned base = (unsigned)((wm + mt * 16 + g) * ROWB) + ka;
                a[mt][0] = lds32(As + base);
                a[mt][1] = lds32(As + base + 8 * ROWB);
                a[mt][2] = lds32(As + base + 16);
                a[mt][3] = lds32(As + base + 8 * ROWB + 16);
            }
            unsigned b[8][2];
            #pragma unroll
            for (int nb = 0; nb < 8; ++nb) {
                unsigned base = (unsigned)((wn + nb * 8 + g) * ROWB) + ka;
                b[nb][0] = lds32(Bs + base);
                b[nb][1] = lds32(Bs + base + 16);
            }
            #pragma unroll
            for (int mt = 0; mt < 2; ++mt)
                #pragma unroll
                for (int nb = 0; nb < 8; ++nb)
                    MMAF16(acc[mt][nb], a[mt], b[nb][0], b[nb][1]);
        }
        __syncthreads();
        if (c + NSTAGES < NCHUNK) load_stage(c + NSTAGES);
        else cp_commit();  // keep wait_group accounting uniform
    }

    // epilogue: acc -> g_C
    float* cbase = g_C + (size_t)(by * 128 + wm) * 8192 + bx * 128 + wn;
    #pragma unroll
    for (int mt = 0; mt < 2; ++mt)
        #pragma unroll
        for (int nb = 0; nb < 8; ++nb) {
            float* p0 = cbase + (size_t)(mt * 16 + g) * 8192 + nb * 8 + 2 * tig;
            *(float2*)p0 = make_float2(acc[mt][nb][0], acc[mt][nb][1]);
            *(float2*)(p0 + 8 * 8192) = make_float2(acc[mt][nb][2], acc[mt][nb][3]);
        }
}

// ============================================================================
// Per-pair epilogue -> scores[i][j]. Softmax weights register-resident;
// Gram read as broadcast float4.
// ============================================================================
__global__ void __launch_bounds__(64) scores_kernel(const int* __restrict__ s_l) {
    __shared__ float A0s[RDIM * 65];
    __shared__ float Gs [RDIM * RDIM];
    __shared__ float rn [RDIM];
    __shared__ float part[2];

    const int j = blockIdx.x, i = blockIdx.y;
    const int tid = threadIdx.x;
    const int L = s_l[j];

    const float* pc = g_C + (size_t)(i * RDIM) * 8192 + j * 64;
    for (int idx = tid; idx < RDIM * WDIM; idx += 64) {
        int r = idx >> 6, w = idx & 63;
        A0s[r * 65 + w] = pc[(size_t)r * 8192 + w];
    }
    const float* pg = g_gram + i * (RDIM * RDIM);
    for (int idx = tid; idx < RDIM * RDIM; idx += 64) Gs[idx] = pg[idx];
    __syncthreads();

    if (tid < RDIM) {
        float sum = 0.f;
        for (int w2 = 0; w2 < L; ++w2) {
            float x = A0s[tid * 65 + w2];
            x = (x > 0.f) ? x : 0.1f * x;
            sum += x * x;
        }
        rn[tid] = 9.0f / (sqrtf(sum) + 1e-8f);
    }
    __syncthreads();

    float t = 0.f;
    if (tid < L) {
        const int w = tid;
        float e[RDIM];
        float m = -1e30f;
        #pragma unroll
        for (int r = 0; r < RDIM; ++r) {
            float x = A0s[r * 65 + w];
            x = (x > 0.f) ? x : 0.1f * x;
            x *= rn[r];
            e[r] = x;
            m = fmaxf(m, x);
        }
        float se = 0.f, num = 0.f;
        #pragma unroll
        for (int r = 0; r < RDIM; ++r) {
            float ev = __expf(e[r] - m);
            e[r] = ev;
            se += ev;
            num += ev * A0s[r * 65 + w];
        }
        float quad = 0.f;
        #pragma unroll
        for (int r = 0; r < RDIM; ++r) {
            const float4* gr = (const float4*)(Gs + r * RDIM);
            float v = 0.f;
            #pragma unroll
            for (int q = 0; q < RDIM / 4; ++q) {
                float4 gv = gr[q];
                v += gv.x * e[4 * q] + gv.y * e[4 * q + 1]
                   + gv.z * e[4 * q + 2] + gv.w * e[4 * q + 3];
            }
            quad += e[r] * v;
        }
        quad = fmaxf(quad, 0.f);
        float nwei  = sqrtf(quad) / se;
        float numn  = num / se;
        float ncv   = g_ncap[j * WDIM + w];
        float denom = fmaxf(ncv * nwei, 1e-8f);
        float rowv  = numn / denom;
        t = __expf(6.0f * rowv);
    }
    #pragma unroll
    for (int o = 16; o; o >>= 1) t += __shfl_down_sync(0xffffffffu, t, o);
    if ((tid & 31) == 0) part[tid >> 5] = t;
    __syncthreads();
    if (tid == 0) g_scores[i * BDIM + j] = logf(part[0] + part[1]) / 6.0f;
}

// ============================================================================
// Hardest-negative hinge loss
// ============================================================================
__global__ void __launch_bounds__(128) loss_kernel(float* __restrict__ out) {
    __shared__ float red[128];
    const int t = threadIdx.x;
    const float di = g_scores[t * BDIM + t];
    float ms = 0.f, mi = 0.f;
    for (int k = 0; k < BDIM; ++k) {
        if (k == t) continue;
        ms = fmaxf(ms, fmaxf(0.f, 0.2f + g_scores[t * BDIM + k] - di));
        mi = fmaxf(mi, fmaxf(0.f, 0.2f + g_scores[k * BDIM + t] - di));
    }
    red[t] = ms + mi;
    __syncthreads();
    for (int st = 64; st > 0; st >>= 1) {
        if (t < st) red[t] += red[t + st];
        __syncthreads();
    }
    if (t == 0) out[0] = red[0];
}

// ============================================================================
extern "C" void kernel_launch(void* const* d_in, const int* in_sizes, int n_in,
                              void* d_out, int out_size) {
    const float* im = (const float*)d_in[0];
    const float* s  = (const float*)d_in[1];
    const int*   sl = (const int*)d_in[2];
    float* out = (float*)d_out;

    cudaFuncSetAttribute(gemm_hmma, cudaFuncAttributeMaxDynamicSharedMemorySize,
                         NSTAGES * STAGE_BYTES);

    convert_im_kernel<<<(BDIM * RDIM * DDIM / 4 + 255) / 256, 256>>>(im);
    convert_s_kernel<<<(BDIM * WDIM * DDIM / 4 + 255) / 256, 256>>>(s);
    gram_kernel<<<BDIM, 256>>>(im);
    ncap_kernel<<<(BDIM * WDIM) / 8, 256>>>(s);
    gemm_hmma<<<dim3(64, 36), 256, NSTAGES * STAGE_BYTES>>>();
    scores_kernel<<<dim3(BDIM, BDIM), 64>>>(sl);
    loss_kernel<<<1, 128>>>(out);
}

// round 9
// speedup vs baseline: 7.1902x; 1.1449x over previous
#include <cuda_runtime.h>
#include <cuda_fp16.h>
#include <cstdint>
#include <math.h>

#define BDIM 128
#define RDIM 36
#define WDIM 64
#define DDIM 1024

// ---------------- device globals (no runtime allocation) ----------------
__device__ __align__(128) float g_C[(size_t)BDIM * RDIM * BDIM * WDIM];   // [4608][8192]
__device__ __align__(128) __half g_A[(size_t)BDIM * RDIM * DDIM];         // fp16(im)
__device__ __align__(128) __half g_B[(size_t)BDIM * WDIM * DDIM];         // fp16(s)
__device__ float g_gram[BDIM * RDIM * RDIM];
__device__ float g_ncap[BDIM * WDIM];
__device__ float g_scores[BDIM * BDIM];

// ---------------- PTX helpers (baseline compute_103-safe only) ----------------
__device__ __forceinline__ unsigned su32(const void* p) {
    unsigned a;
    asm("{ .reg .u64 t; cvta.to.shared.u64 t, %1; cvt.u32.u64 %0, t; }" : "=r"(a) : "l"(p));
    return a;
}
__device__ __forceinline__ void cpa16_s(unsigned dst, const void* src) {
    asm volatile("cp.async.cg.shared.global [%0], [%1], 16;" :: "r"(dst), "l"(src));
}
__device__ __forceinline__ void cp_commit() { asm volatile("cp.async.commit_group;"); }

#define LDSM4(r, addr) \
    asm volatile("ldmatrix.sync.aligned.m8n8.x4.shared.b16 {%0,%1,%2,%3}, [%4];" \
                 : "=r"((r)[0]), "=r"((r)[1]), "=r"((r)[2]), "=r"((r)[3]) : "r"(addr))

#define MMAF16(d, a, b0v, b1v) \
    asm volatile("mma.sync.aligned.m16n8k16.row.col.f32.f16.f16.f32 " \
                 "{%0,%1,%2,%3}, {%4,%5,%6,%7}, {%8,%9}, {%0,%1,%2,%3};" \
                 : "+f"((d)[0]), "+f"((d)[1]), "+f"((d)[2]), "+f"((d)[3]) \
                 : "r"((a)[0]), "r"((a)[1]), "r"((a)[2]), "r"((a)[3]), "r"(b0v), "r"(b1v))

// ============================================================================
// Converts. Device globals referenced DIRECTLY in device code (host-side
// symbol decay -> host shadow; GB300 ATS accepts it silently).
// ============================================================================
__global__ void __launch_bounds__(256) convert_im_kernel(const float* __restrict__ im) {
    int i = blockIdx.x * 256 + threadIdx.x;                 // over float4s
    if (i >= BDIM * RDIM * DDIM / 4) return;
    float4 x = ((const float4*)im)[i];
    __half2* ap = (__half2*)g_A;
    ap[2 * i]     = __half2(__float2half_rn(x.x), __float2half_rn(x.y));
    ap[2 * i + 1] = __half2(__float2half_rn(x.z), __float2half_rn(x.w));
}

__global__ void __launch_bounds__(256) convert_s_kernel(const float* __restrict__ s) {
    int i = blockIdx.x * 256 + threadIdx.x;
    if (i >= BDIM * WDIM * DDIM / 4) return;
    float4 x = ((const float4*)s)[i];
    __half2* bp = (__half2*)g_B;
    bp[2 * i]     = __half2(__float2half_rn(x.x), __float2half_rn(x.y));
    bp[2 * i + 1] = __half2(__float2half_rn(x.z), __float2half_rn(x.w));
}

// ============================================================================
// Gram matrices (symmetric)
// ============================================================================
__global__ void __launch_bounds__(256) gram_kernel(const float* __restrict__ im) {
    const int i = blockIdx.x;
    const int warp = threadIdx.x >> 5, lane = threadIdx.x & 31;
    const float4* base = (const float4*)(im + (size_t)i * RDIM * DDIM);
    for (int p = warp; p < RDIM * RDIM; p += 8) {
        const int r1 = p / RDIM, r2 = p - r1 * RDIM;
        if (r1 > r2) continue;
        const float4* A = base + r1 * (DDIM / 4);
        const float4* B = base + r2 * (DDIM / 4);
        float sum = 0.f;
        for (int q = lane; q < DDIM / 4; q += 32) {
            float4 a = A[q], b = B[q];
            sum += a.x * b.x + a.y * b.y + a.z * b.z + a.w * b.w;
        }
        #pragma unroll
        for (int o = 16; o; o >>= 1) sum += __shfl_down_sync(0xffffffffu, sum, o);
        if (lane == 0) {
            g_gram[i * (RDIM * RDIM) + r1 * RDIM + r2] = sum;
            g_gram[i * (RDIM * RDIM) + r2 * RDIM + r1] = sum;
        }
    }
}

// ============================================================================
// Caption word norms
// ============================================================================
__global__ void __launch_bounds__(256) ncap_kernel(const float* __restrict__ s) {
    const int gw = blockIdx.x * 8 + (threadIdx.x >> 5);
    const int lane = threadIdx.x & 31;
    const float4* row = (const float4*)(s + (size_t)gw * DDIM);
    float sum = 0.f;
    for (int q = lane; q < DDIM / 4; q += 32) {
        float4 a = row[q];
        sum += a.x * a.x + a.y * a.y + a.z * a.z + a.w * a.w;
    }
    #pragma unroll
    for (int o = 16; o; o >>= 1) sum += __shfl_down_sync(0xffffffffu, sum, o);
    if (lane == 0) g_ncap[gw] = sqrtf(sum);
}

// ============================================================================
// HMMA GEMM (pure fp16): C = fp16(A) * fp16(B)^T, fp32 accumulate
// CTA 128x128, 8 warps (4x2), warp tile 32x64, K-chunk 64, 3-stage pipeline,
// 2 CTAs/SM. Fragments via ldmatrix.x4.
// ============================================================================
#define ROWB 144                         // 64 fp16 = 128 B + 16 B pad (conflict-free)
#define TEN_BYTES (128 * ROWB)           // 18432 B per tensor tile
#define STAGE_BYTES (2 * TEN_BYTES)      // 36864 B
#define NSTAGES 3
#define NCHUNK 16                        // 1024 / 64

__global__ void __launch_bounds__(256, 2) gemm_hmma() {
    extern __shared__ __align__(128) unsigned char dsm[];
    const int tid = threadIdx.x, wid = tid >> 5, lane = tid & 31;
    const int bx = blockIdx.x;  // N tile
    const int by = blockIdx.y;  // M tile
    const int wm = (wid & 3) * 32, wn = (wid >> 2) * 64;
    const int g = lane >> 2, tig = lane & 3;
    const unsigned sbase = su32(dsm);

    // ldmatrix lane->row/col mapping (derived; matches m16n8k16 frag layout)
    const unsigned a_off = (unsigned)((lane & 15) * ROWB + ((lane >> 4) << 4));
    const unsigned b_off = (unsigned)(((lane & 7) + ((lane >> 4) << 3)) * ROWB
                                      + (((lane >> 3) & 1) << 4));

    const char* gA = (const char*)g_A + (size_t)by * 128 * 2048;
    const char* gB = (const char*)g_B + (size_t)bx * 128 * 2048;

    float acc[2][8][4];
    #pragma unroll
    for (int mt = 0; mt < 2; ++mt)
        #pragma unroll
        for (int nt = 0; nt < 8; ++nt)
            #pragma unroll
            for (int q = 0; q < 4; ++q) acc[mt][nt][q] = 0.f;

    auto load_stage = [&](int c) {
        const unsigned tb = sbase + (unsigned)(c % NSTAGES) * STAGE_BYTES;
        const int kb = c * 128;  // byte offset within 2048B row
        #pragma unroll
        for (int it = 0; it < 8; ++it) {
            int idx = it * 256 + tid;            // 0..2047
            const char* gbase = (idx < 1024) ? gA : gB;
            int ten = idx >> 10;
            int rem = idx & 1023;
            int row = rem >> 3, q = rem & 7;
            cpa16_s(tb + ten * TEN_BYTES + row * ROWB + q * 16,
                    gbase + (size_t)row * 2048 + kb + q * 16);
        }
        cp_commit();
    };

    load_stage(0);
    load_stage(1);
    load_stage(2);

    for (int c = 0; c < NCHUNK; ++c) {
        asm volatile("cp.async.wait_group 2;" ::: "memory");
        __syncthreads();

        const unsigned tb = sbase + (unsigned)(c % NSTAGES) * STAGE_BYTES;
        const unsigned As = tb + (unsigned)(wm * ROWB) + a_off;
        const unsigned Bs = tb + TEN_BYTES + (unsigned)(wn * ROWB) + b_off;

        #pragma unroll
        for (int kk = 0; kk < 4; ++kk) {
            const unsigned kb = (unsigned)(kk * 32);

            unsigned a[2][4];
            #pragma unroll
            for (int mt = 0; mt < 2; ++mt)
                LDSM4(a[mt], As + (unsigned)(mt * 16 * ROWB) + kb);

            #pragma unroll
            for (int nbp = 0; nbp < 4; ++nbp) {
                unsigned b[4];
                LDSM4(b, Bs + (unsigned)(nbp * 16 * ROWB) + kb);
                #pragma unroll
                for (int mt = 0; mt < 2; ++mt) {
                    MMAF16(acc[mt][2 * nbp + 0], a[mt], b[0], b[1]);
                    MMAF16(acc[mt][2 * nbp + 1], a[mt], b[2], b[3]);
                }
            }
        }
        __syncthreads();
        if (c + NSTAGES < NCHUNK) load_stage(c + NSTAGES);
        else cp_commit();  // keep wait_group accounting uniform
    }

    // epilogue: acc -> g_C
    float* cbase = g_C + (size_t)(by * 128 + wm) * 8192 + bx * 128 + wn;
    #pragma unroll
    for (int mt = 0; mt < 2; ++mt)
        #pragma unroll
        for (int nb = 0; nb < 8; ++nb) {
            float* p0 = cbase + (size_t)(mt * 16 + g) * 8192 + nb * 8 + 2 * tig;
            *(float2*)p0 = make_float2(acc[mt][nb][0], acc[mt][nb][1]);
            *(float2*)(p0 + 8 * 8192) = make_float2(acc[mt][nb][2], acc[mt][nb][3]);
        }
}

// ============================================================================
// Per-pair epilogue -> scores[i][j]. Vectorized float4 staging of C and G;
// softmax weights register-resident; Gram read as broadcast float4.
// ============================================================================
#define A0STRIDE 68   // float4-aligned, conflict-free

__global__ void __launch_bounds__(64) scores_kernel(const int* __restrict__ s_l) {
    __shared__ float A0s[RDIM * A0STRIDE];
    __shared__ float Gs [RDIM * RDIM];
    __shared__ float rn [RDIM];
    __shared__ float part[2];

    const int j = blockIdx.x, i = blockIdx.y;
    const int tid = threadIdx.x;
    const int L = s_l[j];

    // C tile: 36 rows x 16 float4
    const float4* pc4 = (const float4*)(g_C + (size_t)(i * RDIM) * 8192 + j * 64);
    #pragma unroll
    for (int idx = tid; idx < RDIM * 16; idx += 64) {
        int r = idx >> 4, q = idx & 15;
        *(float4*)(A0s + r * A0STRIDE + 4 * q) = pc4[(size_t)r * 2048 + q];
    }
    // Gram: 324 float4
    const float4* pg4 = (const float4*)(g_gram + i * (RDIM * RDIM));
    for (int idx = tid; idx < (RDIM * RDIM) / 4; idx += 64)
        ((float4*)Gs)[idx] = pg4[idx];
    __syncthreads();

    if (tid < RDIM) {
        float sum = 0.f;
        for (int w2 = 0; w2 < L; ++w2) {
            float x = A0s[tid * A0STRIDE + w2];
            x = (x > 0.f) ? x : 0.1f * x;
            sum += x * x;
        }
        rn[tid] = 9.0f / (sqrtf(sum) + 1e-8f);
    }
    __syncthreads();

    float t = 0.f;
    if (tid < L) {
        const int w = tid;
        float e[RDIM];
        float m = -1e30f;
        #pragma unroll
        for (int r = 0; r < RDIM; ++r) {
            float x = A0s[r * A0STRIDE + w];
            x = (x > 0.f) ? x : 0.1f * x;
            x *= rn[r];
            e[r] = x;
            m = fmaxf(m, x);
        }
        float se = 0.f, num = 0.f;
        #pragma unroll
        for (int r = 0; r < RDIM; ++r) {
            float ev = __expf(e[r] - m);
            e[r] = ev;
            se += ev;
            num += ev * A0s[r * A0STRIDE + w];
        }
        float quad = 0.f;
        #pragma unroll
        for (int r = 0; r < RDIM; ++r) {
            const float4* gr = (const float4*)(Gs + r * RDIM);
            float v = 0.f;
            #pragma unroll
            for (int q = 0; q < RDIM / 4; ++q) {
                float4 gv = gr[q];
                v += gv.x * e[4 * q] + gv.y * e[4 * q + 1]
                   + gv.z * e[4 * q + 2] + gv.w * e[4 * q + 3];
            }
            quad += e[r] * v;
        }
        quad = fmaxf(quad, 0.f);
        float nwei  = sqrtf(quad) / se;
        float numn  = num / se;
        float ncv   = g_ncap[j * WDIM + w];
        float denom = fmaxf(ncv * nwei, 1e-8f);
        float rowv  = numn / denom;
        t = __expf(6.0f * rowv);
    }
    #pragma unroll
    for (int o = 16; o; o >>= 1) t += __shfl_down_sync(0xffffffffu, t, o);
    if ((tid & 31) == 0) part[tid >> 5] = t;
    __syncthreads();
    if (tid == 0) g_scores[i * BDIM + j] = logf(part[0] + part[1]) / 6.0f;
}

// ============================================================================
// Hardest-negative hinge loss
// ============================================================================
__global__ void __launch_bounds__(128) loss_kernel(float* __restrict__ out) {
    __shared__ float red[128];
    const int t = threadIdx.x;
    const float di = g_scores[t * BDIM + t];
    float ms = 0.f, mi = 0.f;
    for (int k = 0; k < BDIM; ++k) {
        if (k == t) continue;
        ms = fmaxf(ms, fmaxf(0.f, 0.2f + g_scores[t * BDIM + k] - di));
        mi = fmaxf(mi, fmaxf(0.f, 0.2f + g_scores[k * BDIM + t] - di));
    }
    red[t] = ms + mi;
    __syncthreads();
    for (int st = 64; st > 0; st >>= 1) {
        if (t < st) red[t] += red[t + st];
        __syncthreads();
    }
    if (t == 0) out[0] = red[0];
}

// ============================================================================
extern "C" void kernel_launch(void* const* d_in, const int* in_sizes, int n_in,
                              void* d_out, int out_size) {
    const float* im = (const float*)d_in[0];
    const float* s  = (const float*)d_in[1];
    const int*   sl = (const int*)d_in[2];
    float* out = (float*)d_out;

    cudaFuncSetAttribute(gemm_hmma, cudaFuncAttributeMaxDynamicSharedMemorySize,
                         NSTAGES * STAGE_BYTES);

    convert_im_kernel<<<(BDIM * RDIM * DDIM / 4 + 255) / 256, 256>>>(im);
    convert_s_kernel<<<(BDIM * WDIM * DDIM / 4 + 255) / 256, 256>>>(s);
    gram_kernel<<<BDIM, 256>>>(im);
    ncap_kernel<<<(BDIM * WDIM) / 8, 256>>>(s);
    gemm_hmma<<<dim3(64, 36), 256, NSTAGES * STAGE_BYTES>>>();
    scores_kernel<<<dim3(BDIM, BDIM), 64>>>(sl);
    loss_kernel<<<1, 128>>>(out);
}